// round 14
// baseline (speedup 1.0000x reference)
#include <cuda_runtime.h>
#include <cuda_fp16.h>
#include <cstdint>

#define HEADS 8
#define DIM_HEAD 64
#define NB 4
#define NC 512
#define NL 2048
#define HD 512
#define F3 1536
#define QSCALE (0.125f * 1.4426950408889634f)

// Scratch (device globals; no allocations allowed) — all fp16
__device__ __half g_q[(size_t)NB * HEADS * NL * DIM_HEAD];   // [b,h][l][d]  pre-scaled
__device__ __half g_k[(size_t)NB * HEADS * NL * DIM_HEAD];   // [b,h][l][d]
__device__ __half g_v[(size_t)NB * HEADS * DIM_HEAD * NL];   // [b,h][d][l]
__device__ __half g_attn[(size_t)NB * NL * HD];              // [b][l][c]
__device__ __half g_xt[(size_t)NB * NL * NC];                // [b][l][c]
__device__ __half g_wqt[(size_t)F3 * NC];                    // [f][c]
__device__ __half g_wot[(size_t)NC * HD];                    // [c_out][hd]

__device__ __forceinline__ void mma_f16(float d[4],
                                        uint32_t a0, uint32_t a1, uint32_t a2, uint32_t a3,
                                        uint32_t b0, uint32_t b1) {
    asm volatile(
        "mma.sync.aligned.m16n8k16.row.col.f32.f16.f16.f32 "
        "{%0,%1,%2,%3}, {%4,%5,%6,%7}, {%8,%9}, {%0,%1,%2,%3};"
        : "+f"(d[0]), "+f"(d[1]), "+f"(d[2]), "+f"(d[3])
        : "r"(a0), "r"(a1), "r"(a2), "r"(a3), "r"(b0), "r"(b1));
}

__device__ __forceinline__ void cp16(void* smem, const void* g) {
    uint32_t s = (uint32_t)__cvta_generic_to_shared(smem);
    asm volatile("cp.async.cg.shared.global [%0], [%1], 16;" :: "r"(s), "l"(g));
}
#define CP_COMMIT() asm volatile("cp.async.commit_group;")
#define CP_WAIT(n)  asm volatile("cp.async.wait_group %0;" :: "n"(n))

__device__ __forceinline__ void ldsm4(uint32_t& r0, uint32_t& r1, uint32_t& r2, uint32_t& r3,
                                      const __half* p) {
    uint32_t a = (uint32_t)__cvta_generic_to_shared(p);
    asm volatile("ldmatrix.sync.aligned.m8n8.x4.shared.b16 {%0,%1,%2,%3}, [%4];"
                 : "=r"(r0), "=r"(r1), "=r"(r2), "=r"(r3) : "r"(a));
}

// two fp16 exp2's in one MUFU op
__device__ __forceinline__ uint32_t h2ex2(uint32_t x) {
    uint32_t r;
    asm("ex2.approx.f16x2 %0, %1;" : "=r"(r) : "r"(x));
    return r;
}

// ---------------------------------------------------------------------------
// Merged transpose + fp16 round for all three inputs (one launch).
// ---------------------------------------------------------------------------
__global__ void cvt_all(const float* __restrict__ x,
                        const float* __restrict__ wq,
                        const float* __restrict__ wo,
                        __half* __restrict__ xt,
                        __half* __restrict__ wqt,
                        __half* __restrict__ wot)
{
    __shared__ float t[32][33];
    int bid = blockIdx.x;
    const float* in;
    __half* out;
    int C;
    if (bid < 768)        { in = wq; out = wqt; C = F3; }
    else if (bid < 1024)  { bid -= 768;  in = wo; out = wot; C = HD; }
    else {
        bid -= 1024;
        int bz = bid >> 10;
        bid &= 1023;
        in  = x  + (size_t)bz * NC * NL;
        out = xt + (size_t)bz * NL * NC;
        C = NL;
    }
    const int tpr = C / 32;
    const int c0 = (bid % tpr) * 32, r0 = (bid / tpr) * 32;
    const int tx = threadIdx.x, ty = threadIdx.y;
#pragma unroll
    for (int rr = ty; rr < 32; rr += 8)
        t[rr][tx] = in[(size_t)(r0 + rr) * C + c0 + tx];
    __syncthreads();
#pragma unroll
    for (int rr = ty; rr < 32; rr += 8)
        out[(size_t)(c0 + rr) * NC + r0 + tx] = __float2half_rn(t[tx][rr]);
}

// ---------------------------------------------------------------------------
// QKV GEMM (unchanged R13): CTA 128x128, BK=64, 3-stage cp.async.
// Routes to g_q (scaled)/g_k/g_v fp16.
// ---------------------------------------------------------------------------
#define GSH 72
__global__ __launch_bounds__(256) void gemm_qkv(
    const __half* __restrict__ W, const __half* __restrict__ X)
{
    extern __shared__ __half gsm[];
    const int STAGE = 2 * 128 * GSH;
    const int K = NC, N = NL;

    const int b = blockIdx.z;
    const __half* Xb = X + (size_t)b * N * K;

    const int m0 = blockIdx.y * 128;
    const int n0 = blockIdx.x * 128;
    const int tid  = threadIdx.x;
    const int warp = tid >> 5, lane = tid & 31;
    const int row  = lane >> 2, colk = lane & 3;
    const int wm = (warp >> 1) * 32, wn = (warp & 1) * 64;
    const int aRow = (lane & 7) + ((lane >> 3) & 1) * 8, aCol = (lane >> 4) * 8;
    const int bRow = (lane & 7) + (lane >> 4) * 8,       bCol = ((lane >> 3) & 1) * 8;

    float acc[2][8][4];
#pragma unroll
    for (int i = 0; i < 2; i++)
#pragma unroll
        for (int j = 0; j < 8; j++)
#pragma unroll
            for (int c = 0; c < 4; c++) acc[i][j][c] = 0.f;

    auto load_stage = [&](int st, int k0) {
        __half* A = gsm + st * STAGE;
        __half* B = A + 128 * GSH;
#pragma unroll
        for (int t = 0; t < 4; t++) {
            int v  = tid + t * 256;
            int rw = v >> 3;
            int ch = (v & 7) * 8;
            cp16(&A[rw * GSH + ch], W  + (size_t)(m0 + rw) * K + k0 + ch);
            cp16(&B[rw * GSH + ch], Xb + (size_t)(n0 + rw) * K + k0 + ch);
        }
    };

    const int KT = K / 64;
    load_stage(0, 0);  CP_COMMIT();
    load_stage(1, 64); CP_COMMIT();

    int st = 0;
    for (int kt = 0; kt < KT; kt++) {
        CP_WAIT(1);
        __syncthreads();
        if (kt + 2 < KT) {
            load_stage((kt + 2) % 3, (kt + 2) * 64);
            CP_COMMIT();
        }
        const __half* A = gsm + st * STAGE;
        const __half* B = A + 128 * GSH;
        st = (st + 1 == 3) ? 0 : st + 1;

#pragma unroll
        for (int ks = 0; ks < 4; ks++) {
            const int kb = ks * 16;
            uint32_t a[2][4];
            ldsm4(a[0][0], a[0][1], a[0][2], a[0][3], &A[(wm + aRow) * GSH + kb + aCol]);
            ldsm4(a[1][0], a[1][1], a[1][2], a[1][3], &A[(wm + 16 + aRow) * GSH + kb + aCol]);
#pragma unroll
            for (int jj = 0; jj < 4; jj++) {
                uint32_t b0, b1, b2, b3;
                ldsm4(b0, b1, b2, b3, &B[(wn + jj * 16 + bRow) * GSH + kb + bCol]);
#pragma unroll
                for (int i = 0; i < 2; i++) {
                    mma_f16(acc[i][2 * jj],     a[i][0], a[i][1], a[i][2], a[i][3], b0, b1);
                    mma_f16(acc[i][2 * jj + 1], a[i][0], a[i][1], a[i][2], a[i][3], b2, b3);
                }
            }
        }
    }

    const int sec = m0 >> 9;              // 0=q, 1=k, 2=v (CTA-uniform)
#pragma unroll
    for (int i = 0; i < 2; i++) {
        int mloc = (m0 & 511) + wm + 16 * i + row;
        int hh = mloc >> 6, dd = mloc & 63;
        size_t bh = (size_t)b * HEADS + hh;
#pragma unroll
        for (int j = 0; j < 8; j++) {
            int n = n0 + wn + j * 8 + colk * 2;
            float v0 = acc[i][j][0], v1 = acc[i][j][1];
            float v2 = acc[i][j][2], v3 = acc[i][j][3];
            if (sec == 0) {
                __half* p = g_q + (bh * NL + n) * 64 + dd;
                p[0]  = __float2half_rn(v0 * QSCALE);
                p[64] = __float2half_rn(v1 * QSCALE);
                p[8]  = __float2half_rn(v2 * QSCALE);
                p[72] = __float2half_rn(v3 * QSCALE);
            } else if (sec == 1) {
                __half* p = g_k + (bh * NL + n) * 64 + dd;
                p[0]  = __float2half_rn(v0);
                p[64] = __float2half_rn(v1);
                p[8]  = __float2half_rn(v2);
                p[72] = __float2half_rn(v3);
            } else {
                __half* p = g_v + (bh * 64 + dd) * NL + n;
                *(__half2*)p            = __floats2half2_rn(v0, v1);
                *(__half2*)(p + 8 * NL) = __floats2half2_rn(v2, v3);
            }
        }
    }
}

// ---------------------------------------------------------------------------
// Output projection: Y[b][m][n] = sum_k wot[m][k] * attn[b][n][k] + bias[m].
// CTA 64x128, warp tile 16x64 (8 warps, 4m x 2n), BK=64, 2-stage pipeline.
// Low register count -> 3 CTAs/SM (24 warps) for latency hiding.
// ---------------------------------------------------------------------------
#define OSH 72
__global__ __launch_bounds__(256, 3) void gemm_out(
    const __half* __restrict__ W, const __half* __restrict__ X,
    float* __restrict__ Y, const float* __restrict__ bias)
{
    extern __shared__ __half osm[];       // 2 stages x (A 64x72 + B 128x72)
    const int STAGE = (64 + 128) * OSH;
    const int K = NC, N = NL, M = NC;

    const int b = blockIdx.z;
    const __half* Xb = X + (size_t)b * N * K;

    const int m0 = blockIdx.y * 64;
    const int n0 = blockIdx.x * 128;
    const int tid  = threadIdx.x;
    const int warp = tid >> 5, lane = tid & 31;
    const int row  = lane >> 2, colk = lane & 3;
    const int wm = (warp >> 1) * 16, wn = (warp & 1) * 64;
    const int aRow = (lane & 7) + ((lane >> 3) & 1) * 8, aCol = (lane >> 4) * 8;
    const int bRow = (lane & 7) + (lane >> 4) * 8,       bCol = ((lane >> 3) & 1) * 8;

    float acc[8][4];
#pragma unroll
    for (int j = 0; j < 8; j++)
#pragma unroll
        for (int c = 0; c < 4; c++) acc[j][c] = 0.f;

    auto load_stage = [&](int st, int k0) {
        __half* A = osm + st * STAGE;
        __half* B = A + 64 * OSH;
#pragma unroll
        for (int t = 0; t < 2; t++) {               // A: 64 rows
            int v  = tid + t * 256;                 // 0..511
            int rw = v >> 3;
            int ch = (v & 7) * 8;
            cp16(&A[rw * OSH + ch], W + (size_t)(m0 + rw) * K + k0 + ch);
        }
#pragma unroll
        for (int t = 0; t < 4; t++) {               // B: 128 rows
            int v  = tid + t * 256;                 // 0..1023
            int rw = v >> 3;
            int ch = (v & 7) * 8;
            cp16(&B[rw * OSH + ch], Xb + (size_t)(n0 + rw) * K + k0 + ch);
        }
    };

    load_stage(0, 0);
    CP_COMMIT();

    const int KT = K / 64;
    for (int kt = 0; kt < KT; kt++) {
        CP_WAIT(0);          // stage kt loaded
        __syncthreads();     // visible; all warps done with stage kt-1
        if (kt + 1 < KT) {
            load_stage((kt + 1) & 1, (kt + 1) * 64);   // overwrites stage kt-1
            CP_COMMIT();
        }
        const __half* A = osm + (kt & 1) * STAGE;
        const __half* B = A + 64 * OSH;

#pragma unroll
        for (int ks = 0; ks < 4; ks++) {
            const int kb = ks * 16;
            uint32_t a0, a1, a2, a3;
            ldsm4(a0, a1, a2, a3, &A[(wm + aRow) * OSH + kb + aCol]);
#pragma unroll
            for (int jj = 0; jj < 4; jj++) {
                uint32_t b0, b1, b2, b3;
                ldsm4(b0, b1, b2, b3, &B[(wn + jj * 16 + bRow) * OSH + kb + bCol]);
                mma_f16(acc[2 * jj],     a0, a1, a2, a3, b0, b1);
                mma_f16(acc[2 * jj + 1], a0, a1, a2, a3, b2, b3);
            }
        }
    }

    float* Yb = Y + (size_t)b * M * N;
    const int m = m0 + wm + row;
    const float bv0 = bias[m], bv1 = bias[m + 8];
#pragma unroll
    for (int j = 0; j < 8; j++) {
        int n = n0 + wn + j * 8 + colk * 2;
        Yb[(size_t)m * N + n]           = acc[j][0] + bv0;
        Yb[(size_t)m * N + n + 1]       = acc[j][1] + bv0;
        Yb[(size_t)(m + 8) * N + n]     = acc[j][2] + bv1;
        Yb[(size_t)(m + 8) * N + n + 1] = acc[j][3] + bv1;
    }
}

// ---------------------------------------------------------------------------
// Flash attention (unchanged R13): fp16 mma + LDSM, 128-query CTA, 256 thr,
// double-buffered 128-key stages, hoisted Q fragments, register-resident P,
// no max-subtraction. Smem 90,112 B -> 2 CTAs/SM.
// ---------------------------------------------------------------------------
#define QSM 72
#define KSM 72
#define VSM 136
__global__ __launch_bounds__(256, 2) void attn_f16(void)
{
    extern __shared__ __half sm[];
    __half* Qs = sm;                     // [128][72]     (i, d)
    __half* Ks = Qs + 128 * QSM;         // [2][128][72]  (j, d)
    __half* Vs = Ks + 2 * 128 * KSM;     // [2][64][136]  (d, j)
    __half* Os = Ks;                     // epilogue reuse

    const int bh = blockIdx.y;
    const int b  = bh >> 3;
    const int h  = bh & 7;
    const int i0 = blockIdx.x * 128;

    const __half* qb = g_q + (size_t)bh * NL * 64;
    const __half* kb = g_k + (size_t)bh * NL * 64;
    const __half* vb = g_v + (size_t)bh * 64 * NL;

    const int tid  = threadIdx.x;
    const int warp = tid >> 5, lane = tid & 31;
    const int row  = lane >> 2, colk = lane & 3;
    const int wi   = warp * 16;
    const int aRow = (lane & 7) + ((lane >> 3) & 1) * 8, aCol = (lane >> 4) * 8;
    const int bRow = (lane & 7) + (lane >> 4) * 8,       bCol = ((lane >> 3) & 1) * 8;

    auto load_k = [&](int stg, int j0) {
        __half* K = Ks + stg * 128 * KSM;
#pragma unroll
        for (int t = 0; t < 4; t++) {
            int v  = tid + t * 256;
            int rw = v >> 3;
            int ch = (v & 7) * 8;
            cp16(&K[rw * KSM + ch], kb + (size_t)(j0 + rw) * 64 + ch);
        }
    };
    auto load_v = [&](int stg, int j0) {
        __half* V = Vs + stg * 64 * VSM;
#pragma unroll
        for (int t = 0; t < 4; t++) {
            int v  = tid + t * 256;
            int rw = v >> 4;
            int ch = (v & 15) * 8;
            cp16(&V[rw * VSM + ch], vb + (size_t)rw * NL + j0 + ch);
        }
    };

#pragma unroll
    for (int t = 0; t < 4; t++) {
        int v  = tid + t * 256;
        int rw = v >> 3;
        int ch = (v & 7) * 8;
        cp16(&Qs[rw * QSM + ch], qb + (size_t)(i0 + rw) * 64 + ch);
    }
    load_k(0, 0);
    load_v(0, 0);
    CP_COMMIT();

    CP_WAIT(0);
    __syncthreads();
    uint32_t qf[4][4];
#pragma unroll
    for (int kc = 0; kc < 4; kc++)
        ldsm4(qf[kc][0], qf[kc][1], qf[kc][2], qf[kc][3],
              &Qs[(wi + aRow) * QSM + kc * 16 + aCol]);

    float l0r = 0.f, l1r = 0.f;
    float o[8][4];
#pragma unroll
    for (int df = 0; df < 8; df++)
#pragma unroll
        for (int c = 0; c < 4; c++) o[df][c] = 0.f;

    const int NT = NL / 128;
    for (int jt = 0; jt < NT; jt++) {
        if (jt > 0) {
            CP_WAIT(0);
            __syncthreads();
        }
        if (jt + 1 < NT) {
            load_k((jt + 1) & 1, (jt + 1) * 128);
            load_v((jt + 1) & 1, (jt + 1) * 128);
            CP_COMMIT();
        }
        const __half* K = Ks + (jt & 1) * 128 * KSM;
        const __half* V = Vs + (jt & 1) * 64 * VSM;

#pragma unroll
        for (int sub = 0; sub < 2; sub++) {
            const int jb = sub * 64;

            float s[8][4];
#pragma unroll
            for (int jf = 0; jf < 8; jf++)
#pragma unroll
                for (int c = 0; c < 4; c++) s[jf][c] = 0.f;

#pragma unroll
            for (int kc = 0; kc < 4; kc++) {
                const int kb16 = kc * 16;
#pragma unroll
                for (int jj = 0; jj < 4; jj++) {
                    uint32_t b0, b1, b2, b3;
                    ldsm4(b0, b1, b2, b3, &K[(jb + jj * 16 + bRow) * KSM + kb16 + bCol]);
                    mma_f16(s[2 * jj],     qf[kc][0], qf[kc][1], qf[kc][2], qf[kc][3], b0, b1);
                    mma_f16(s[2 * jj + 1], qf[kc][0], qf[kc][1], qf[kc][2], qf[kc][3], b2, b3);
                }
            }

            uint32_t pl[8], ph[8];
            float rs0 = 0.f, rs1 = 0.f;
#pragma unroll
            for (int jf = 0; jf < 8; jf++) {
                __half2 d0 = __floats2half2_rn(s[jf][0], s[jf][1]);
                __half2 d1 = __floats2half2_rn(s[jf][2], s[jf][3]);
                pl[jf] = h2ex2(*(uint32_t*)&d0);
                ph[jf] = h2ex2(*(uint32_t*)&d1);
                float2 f0 = __half22float2(*(__half2*)&pl[jf]);
                float2 f1 = __half22float2(*(__half2*)&ph[jf]);
                rs0 += f0.x + f0.y;
                rs1 += f1.x + f1.y;
            }
            l0r += rs0;
            l1r += rs1;

#pragma unroll
            for (int kc = 0; kc < 4; kc++) {
                const int kb16 = jb + kc * 16;
                uint32_t a0 = pl[2 * kc],     a1 = ph[2 * kc];
                uint32_t a2 = pl[2 * kc + 1], a3 = ph[2 * kc + 1];
#pragma unroll
                for (int jj = 0; jj < 4; jj++) {
                    uint32_t b0, b1, b2, b3;
                    ldsm4(b0, b1, b2, b3, &V[(jj * 16 + bRow) * VSM + kb16 + bCol]);
                    mma_f16(o[2 * jj],     a0, a1, a2, a3, b0, b1);
                    mma_f16(o[2 * jj + 1], a0, a1, a2, a3, b2, b3);
                }
            }
        }
    }

    l0r += __shfl_xor_sync(0xffffffffu, l0r, 1, 4);
    l0r += __shfl_xor_sync(0xffffffffu, l0r, 2, 4);
    l1r += __shfl_xor_sync(0xffffffffu, l1r, 1, 4);
    l1r += __shfl_xor_sync(0xffffffffu, l1r, 2, 4);
    float inv0 = 1.f / l0r;
    float inv1 = 1.f / l1r;

    __syncthreads();
#pragma unroll
    for (int df = 0; df < 8; df++) {
        int d = df * 8 + colk * 2;
        *(__half2*)&Os[(wi + row) * KSM + d]     = __floats2half2_rn(o[df][0] * inv0, o[df][1] * inv0);
        *(__half2*)&Os[(wi + row + 8) * KSM + d] = __floats2half2_rn(o[df][2] * inv1, o[df][3] * inv1);
    }
    __syncthreads();

    __half* ob = g_attn + ((size_t)b * NL + i0) * HD + h * 64;
#pragma unroll
    for (int t = 0; t < 4; t++) {
        int v  = tid + t * 256;
        int rw = v >> 3;
        int ch = (v & 7) * 8;
        *(uint4*)(ob + (size_t)rw * HD + ch) = *(const uint4*)(&Os[rw * KSM + ch]);
    }
}

// ---------------------------------------------------------------------------
// Launch
// ---------------------------------------------------------------------------
extern "C" void kernel_launch(void* const* d_in, const int* in_sizes, int n_in,
                              void* d_out, int out_size)
{
    const float* x     = (const float*)d_in[0];   // [4, 512, 2048]
    const float* w_qkv = (const float*)d_in[1];   // [512, 1536]
    const float* w_out = (const float*)d_in[2];   // [512, 512]
    const float* b_out = (const float*)d_in[3];   // [512]
    float* y = (float*)d_out;                     // [4, 512, 2048]

    __half *xt, *wqt, *wot, *attn;
    cudaGetSymbolAddress((void**)&xt,   g_xt);
    cudaGetSymbolAddress((void**)&wqt,  g_wqt);
    cudaGetSymbolAddress((void**)&wot,  g_wot);
    cudaGetSymbolAddress((void**)&attn, g_attn);

    // 0) fp16-rounding transposes to k-minor layouts (single launch)
    cvt_all<<<5120, dim3(32, 8)>>>(x, w_qkv, w_out, xt, wqt, wot);

    // 1) QKV projection: M=1536, N=2048, K=512 -> g_q/g_k/g_v (fp16)
    {
        const int gsmem = 3 * 2 * 128 * GSH * (int)sizeof(__half);   // 110,592 B
        cudaFuncSetAttribute(gemm_qkv, cudaFuncAttributeMaxDynamicSharedMemorySize, gsmem);
        dim3 grid(NL / 128, F3 / 128, NB);
        gemm_qkv<<<grid, 256, gsmem>>>(wqt, xt);
    }

    // 2) Flash attention -> g_attn[b][l][c] (fp16)
    {
        const int asmem = (128 * QSM + 2 * 128 * KSM + 2 * 64 * VSM) * (int)sizeof(__half); // 90,112 B
        cudaFuncSetAttribute(attn_f16, cudaFuncAttributeMaxDynamicSharedMemorySize, asmem);
        dim3 grid(NL / 128, NB * HEADS);
        attn_f16<<<grid, 256, asmem>>>();
    }

    // 3) Output projection + bias: M=512, N=2048, K=512 -> fp32 out
    {
        const int osmem = 2 * (64 + 128) * OSH * (int)sizeof(__half);  // 55,296 B
        cudaFuncSetAttribute(gemm_out, cudaFuncAttributeMaxDynamicSharedMemorySize, osmem);
        dim3 grid(NL / 128, NC / 64, NB);   // (16, 8, 4) = 512 CTAs
        gemm_out<<<grid, 256, osmem>>>(wot, attn, y, b_out);
    }
}

// round 15
// speedup vs baseline: 1.0598x; 1.0598x over previous
#include <cuda_runtime.h>
#include <cuda_fp16.h>
#include <cstdint>

#define HEADS 8
#define DIM_HEAD 64
#define NB 4
#define NC 512
#define NL 2048
#define HD 512
#define F3 1536
#define QSCALE (0.125f * 1.4426950408889634f)

// Scratch (device globals; no allocations allowed) — all fp16
__device__ __half g_q[(size_t)NB * HEADS * NL * DIM_HEAD];   // [b,h][l][d]  pre-scaled
__device__ __half g_k[(size_t)NB * HEADS * NL * DIM_HEAD];   // [b,h][l][d]
__device__ __half g_v[(size_t)NB * HEADS * DIM_HEAD * NL];   // [b,h][d][l]
__device__ __half g_attn[(size_t)NB * NL * HD];              // [b][l][c]
__device__ __half g_xt[(size_t)NB * NL * NC];                // [b][l][c]
__device__ __half g_wqt[(size_t)F3 * NC];                    // [f][c]
__device__ __half g_wot[(size_t)NC * HD];                    // [c_out][hd]

__device__ __forceinline__ void mma_f16(float d[4],
                                        uint32_t a0, uint32_t a1, uint32_t a2, uint32_t a3,
                                        uint32_t b0, uint32_t b1) {
    asm volatile(
        "mma.sync.aligned.m16n8k16.row.col.f32.f16.f16.f32 "
        "{%0,%1,%2,%3}, {%4,%5,%6,%7}, {%8,%9}, {%0,%1,%2,%3};"
        : "+f"(d[0]), "+f"(d[1]), "+f"(d[2]), "+f"(d[3])
        : "r"(a0), "r"(a1), "r"(a2), "r"(a3), "r"(b0), "r"(b1));
}

__device__ __forceinline__ void cp16(void* smem, const void* g) {
    uint32_t s = (uint32_t)__cvta_generic_to_shared(smem);
    asm volatile("cp.async.cg.shared.global [%0], [%1], 16;" :: "r"(s), "l"(g));
}
#define CP_COMMIT() asm volatile("cp.async.commit_group;")
#define CP_WAIT(n)  asm volatile("cp.async.wait_group %0;" :: "n"(n))

__device__ __forceinline__ void ldsm4(uint32_t& r0, uint32_t& r1, uint32_t& r2, uint32_t& r3,
                                      const __half* p) {
    uint32_t a = (uint32_t)__cvta_generic_to_shared(p);
    asm volatile("ldmatrix.sync.aligned.m8n8.x4.shared.b16 {%0,%1,%2,%3}, [%4];"
                 : "=r"(r0), "=r"(r1), "=r"(r2), "=r"(r3) : "r"(a));
}

// two fp16 exp2's in one MUFU op
__device__ __forceinline__ uint32_t h2ex2(uint32_t x) {
    uint32_t r;
    asm("ex2.approx.f16x2 %0, %1;" : "=r"(r) : "r"(x));
    return r;
}

// ---------------------------------------------------------------------------
// Merged transpose + fp16 round for all three inputs (one launch).
// ---------------------------------------------------------------------------
__global__ void cvt_all(const float* __restrict__ x,
                        const float* __restrict__ wq,
                        const float* __restrict__ wo,
                        __half* __restrict__ xt,
                        __half* __restrict__ wqt,
                        __half* __restrict__ wot)
{
    __shared__ float t[32][33];
    int bid = blockIdx.x;
    const float* in;
    __half* out;
    int C;
    if (bid < 768)        { in = wq; out = wqt; C = F3; }
    else if (bid < 1024)  { bid -= 768;  in = wo; out = wot; C = HD; }
    else {
        bid -= 1024;
        int bz = bid >> 10;
        bid &= 1023;
        in  = x  + (size_t)bz * NC * NL;
        out = xt + (size_t)bz * NL * NC;
        C = NL;
    }
    const int tpr = C / 32;
    const int c0 = (bid % tpr) * 32, r0 = (bid / tpr) * 32;
    const int tx = threadIdx.x, ty = threadIdx.y;
#pragma unroll
    for (int rr = ty; rr < 32; rr += 8)
        t[rr][tx] = in[(size_t)(r0 + rr) * C + c0 + tx];
    __syncthreads();
#pragma unroll
    for (int rr = ty; rr < 32; rr += 8)
        out[(size_t)(c0 + rr) * NC + r0 + tx] = __float2half_rn(t[tx][rr]);
}

// ---------------------------------------------------------------------------
// GEMM (unified, R13 shape): Y[b][m][n] = sum_k W'[m][k] * X'[b][n][k].
// CTA 128x128, BK=64, 3-stage cp.async, one barrier per k-iter, 8 warps 32x64.
// mode 1: route to g_q (scaled)/g_k/g_v fp16.   mode 0: Y fp32 + bias.
// ---------------------------------------------------------------------------
#define GSH 72
__global__ __launch_bounds__(256) void gemm_f16(
    const __half* __restrict__ W, const __half* __restrict__ X,
    float* __restrict__ Y, const float* __restrict__ bias,
    int M, int N, int K, int mode)
{
    extern __shared__ __half gsm[];
    const int STAGE = 2 * 128 * GSH;

    const int b = blockIdx.z;
    const __half* Xb = X + (size_t)b * N * K;

    const int m0 = blockIdx.y * 128;
    const int n0 = blockIdx.x * 128;
    const int tid  = threadIdx.x;
    const int warp = tid >> 5, lane = tid & 31;
    const int row  = lane >> 2, colk = lane & 3;
    const int wm = (warp >> 1) * 32, wn = (warp & 1) * 64;
    const int aRow = (lane & 7) + ((lane >> 3) & 1) * 8, aCol = (lane >> 4) * 8;
    const int bRow = (lane & 7) + (lane >> 4) * 8,       bCol = ((lane >> 3) & 1) * 8;

    float acc[2][8][4];
#pragma unroll
    for (int i = 0; i < 2; i++)
#pragma unroll
        for (int j = 0; j < 8; j++)
#pragma unroll
            for (int c = 0; c < 4; c++) acc[i][j][c] = 0.f;

    auto load_stage = [&](int st, int k0) {
        __half* A = gsm + st * STAGE;
        __half* B = A + 128 * GSH;
#pragma unroll
        for (int t = 0; t < 4; t++) {
            int v  = tid + t * 256;
            int rw = v >> 3;
            int ch = (v & 7) * 8;
            cp16(&A[rw * GSH + ch], W  + (size_t)(m0 + rw) * K + k0 + ch);
            cp16(&B[rw * GSH + ch], Xb + (size_t)(n0 + rw) * K + k0 + ch);
        }
    };

    const int KT = K / 64;
    load_stage(0, 0);  CP_COMMIT();
    load_stage(1, 64); CP_COMMIT();

    int st = 0;
    for (int kt = 0; kt < KT; kt++) {
        CP_WAIT(1);
        __syncthreads();
        if (kt + 2 < KT) {
            load_stage((kt + 2) % 3, (kt + 2) * 64);
            CP_COMMIT();
        }
        const __half* A = gsm + st * STAGE;
        const __half* B = A + 128 * GSH;
        st = (st + 1 == 3) ? 0 : st + 1;

#pragma unroll
        for (int ks = 0; ks < 4; ks++) {
            const int kb = ks * 16;
            uint32_t a[2][4];
            ldsm4(a[0][0], a[0][1], a[0][2], a[0][3], &A[(wm + aRow) * GSH + kb + aCol]);
            ldsm4(a[1][0], a[1][1], a[1][2], a[1][3], &A[(wm + 16 + aRow) * GSH + kb + aCol]);
#pragma unroll
            for (int jj = 0; jj < 4; jj++) {
                uint32_t b0, b1, b2, b3;
                ldsm4(b0, b1, b2, b3, &B[(wn + jj * 16 + bRow) * GSH + kb + bCol]);
#pragma unroll
                for (int i = 0; i < 2; i++) {
                    mma_f16(acc[i][2 * jj],     a[i][0], a[i][1], a[i][2], a[i][3], b0, b1);
                    mma_f16(acc[i][2 * jj + 1], a[i][0], a[i][1], a[i][2], a[i][3], b2, b3);
                }
            }
        }
    }

    if (mode == 1) {
        const int sec = m0 >> 9;              // 0=q, 1=k, 2=v (CTA-uniform)
#pragma unroll
        for (int i = 0; i < 2; i++) {
            int mloc = (m0 & 511) + wm + 16 * i + row;
            int hh = mloc >> 6, dd = mloc & 63;
            size_t bh = (size_t)b * HEADS + hh;
#pragma unroll
            for (int j = 0; j < 8; j++) {
                int n = n0 + wn + j * 8 + colk * 2;
                float v0 = acc[i][j][0], v1 = acc[i][j][1];
                float v2 = acc[i][j][2], v3 = acc[i][j][3];
                if (sec == 0) {
                    __half* p = g_q + (bh * NL + n) * 64 + dd;
                    p[0]  = __float2half_rn(v0 * QSCALE);
                    p[64] = __float2half_rn(v1 * QSCALE);
                    p[8]  = __float2half_rn(v2 * QSCALE);
                    p[72] = __float2half_rn(v3 * QSCALE);
                } else if (sec == 1) {
                    __half* p = g_k + (bh * NL + n) * 64 + dd;
                    p[0]  = __float2half_rn(v0);
                    p[64] = __float2half_rn(v1);
                    p[8]  = __float2half_rn(v2);
                    p[72] = __float2half_rn(v3);
                } else {
                    __half* p = g_v + (bh * 64 + dd) * NL + n;
                    *(__half2*)p            = __floats2half2_rn(v0, v1);
                    *(__half2*)(p + 8 * NL) = __floats2half2_rn(v2, v3);
                }
            }
        }
    } else {
        float* Yb = Y + (size_t)b * M * N;
#pragma unroll
        for (int i = 0; i < 2; i++) {
            int m = m0 + wm + 16 * i + row;
            float bv0 = bias[m], bv1 = bias[m + 8];
#pragma unroll
            for (int j = 0; j < 8; j++) {
                int n = n0 + wn + j * 8 + colk * 2;
                Yb[(size_t)m * N + n]           = acc[i][j][0] + bv0;
                Yb[(size_t)m * N + n + 1]       = acc[i][j][1] + bv0;
                Yb[(size_t)(m + 8) * N + n]     = acc[i][j][2] + bv1;
                Yb[(size_t)(m + 8) * N + n + 1] = acc[i][j][3] + bv1;
            }
        }
    }
}

// ---------------------------------------------------------------------------
// Flash attention, fp16 mma + LDSM. CTA = (b, h, 128-query tile), 256 threads.
// Double-buffered 128-key stages, hoisted Q fragments, register-resident P,
// no max-subtraction, and row-sums l computed ON THE TENSOR CORE via an
// all-ones B fragment (D[i][*] += sum_j P[i][j]) — no cvt-backs, no shuffles.
// Smem: Qs[128][72] + Ks[2][128][72] + Vs[2][64][136] = 90,112 B -> 2 CTAs/SM.
// ---------------------------------------------------------------------------
#define QSM 72
#define KSM 72
#define VSM 136
__global__ __launch_bounds__(256, 2) void attn_f16(void)
{
    extern __shared__ __half sm[];
    __half* Qs = sm;                     // [128][72]     (i, d)
    __half* Ks = Qs + 128 * QSM;         // [2][128][72]  (j, d)
    __half* Vs = Ks + 2 * 128 * KSM;     // [2][64][136]  (d, j)
    __half* Os = Ks;                     // epilogue reuse

    const int bh = blockIdx.y;
    const int b  = bh >> 3;
    const int h  = bh & 7;
    const int i0 = blockIdx.x * 128;

    const __half* qb = g_q + (size_t)bh * NL * 64;
    const __half* kb = g_k + (size_t)bh * NL * 64;
    const __half* vb = g_v + (size_t)bh * 64 * NL;

    const int tid  = threadIdx.x;
    const int warp = tid >> 5, lane = tid & 31;
    const int row  = lane >> 2, colk = lane & 3;
    const int wi   = warp * 16;
    const int aRow = (lane & 7) + ((lane >> 3) & 1) * 8, aCol = (lane >> 4) * 8;
    const int bRow = (lane & 7) + (lane >> 4) * 8,       bCol = ((lane >> 3) & 1) * 8;
    const uint32_t ONES = 0x3C003C00u;   // half2(1.0, 1.0)

    auto load_k = [&](int stg, int j0) {
        __half* K = Ks + stg * 128 * KSM;
#pragma unroll
        for (int t = 0; t < 4; t++) {
            int v  = tid + t * 256;
            int rw = v >> 3;
            int ch = (v & 7) * 8;
            cp16(&K[rw * KSM + ch], kb + (size_t)(j0 + rw) * 64 + ch);
        }
    };
    auto load_v = [&](int stg, int j0) {
        __half* V = Vs + stg * 64 * VSM;
#pragma unroll
        for (int t = 0; t < 4; t++) {
            int v  = tid + t * 256;
            int rw = v >> 4;
            int ch = (v & 15) * 8;
            cp16(&V[rw * VSM + ch], vb + (size_t)rw * NL + j0 + ch);
        }
    };

#pragma unroll
    for (int t = 0; t < 4; t++) {
        int v  = tid + t * 256;
        int rw = v >> 3;
        int ch = (v & 7) * 8;
        cp16(&Qs[rw * QSM + ch], qb + (size_t)(i0 + rw) * 64 + ch);
    }
    load_k(0, 0);
    load_v(0, 0);
    CP_COMMIT();

    CP_WAIT(0);
    __syncthreads();
    uint32_t qf[4][4];
#pragma unroll
    for (int kc = 0; kc < 4; kc++)
        ldsm4(qf[kc][0], qf[kc][1], qf[kc][2], qf[kc][3],
              &Qs[(wi + aRow) * QSM + kc * 16 + aCol]);

    float lsum[4];
#pragma unroll
    for (int c = 0; c < 4; c++) lsum[c] = 0.f;
    float o[8][4];
#pragma unroll
    for (int df = 0; df < 8; df++)
#pragma unroll
        for (int c = 0; c < 4; c++) o[df][c] = 0.f;

    const int NT = NL / 128;
    for (int jt = 0; jt < NT; jt++) {
        if (jt > 0) {
            CP_WAIT(0);
            __syncthreads();
        }
        if (jt + 1 < NT) {
            load_k((jt + 1) & 1, (jt + 1) * 128);
            load_v((jt + 1) & 1, (jt + 1) * 128);
            CP_COMMIT();
        }
        const __half* K = Ks + (jt & 1) * 128 * KSM;
        const __half* V = Vs + (jt & 1) * 64 * VSM;

#pragma unroll
        for (int sub = 0; sub < 2; sub++) {
            const int jb = sub * 64;

            // S = Q K^T
            float s[8][4];
#pragma unroll
            for (int jf = 0; jf < 8; jf++)
#pragma unroll
                for (int c = 0; c < 4; c++) s[jf][c] = 0.f;

#pragma unroll
            for (int kc = 0; kc < 4; kc++) {
                const int kb16 = kc * 16;
#pragma unroll
                for (int jj = 0; jj < 4; jj++) {
                    uint32_t b0, b1, b2, b3;
                    ldsm4(b0, b1, b2, b3, &K[(jb + jj * 16 + bRow) * KSM + kb16 + bCol]);
                    mma_f16(s[2 * jj],     qf[kc][0], qf[kc][1], qf[kc][2], qf[kc][3], b0, b1);
                    mma_f16(s[2 * jj + 1], qf[kc][0], qf[kc][1], qf[kc][2], qf[kc][3], b2, b3);
                }
            }

            // P = exp2(S); fp16 pairs are the PV A-fragments directly.
            uint32_t pl[8], ph[8];
#pragma unroll
            for (int jf = 0; jf < 8; jf++) {
                __half2 d0 = __floats2half2_rn(s[jf][0], s[jf][1]);
                __half2 d1 = __floats2half2_rn(s[jf][2], s[jf][3]);
                pl[jf] = h2ex2(*(uint32_t*)&d0);
                ph[jf] = h2ex2(*(uint32_t*)&d1);
            }

            // O += P V^T ; l += P * ones (on the tensor pipe)
#pragma unroll
            for (int kc = 0; kc < 4; kc++) {
                const int kb16 = jb + kc * 16;
                uint32_t a0 = pl[2 * kc],     a1 = ph[2 * kc];
                uint32_t a2 = pl[2 * kc + 1], a3 = ph[2 * kc + 1];
                mma_f16(lsum, a0, a1, a2, a3, ONES, ONES);
#pragma unroll
                for (int jj = 0; jj < 4; jj++) {
                    uint32_t b0, b1, b2, b3;
                    ldsm4(b0, b1, b2, b3, &V[(jj * 16 + bRow) * VSM + kb16 + bCol]);
                    mma_f16(o[2 * jj],     a0, a1, a2, a3, b0, b1);
                    mma_f16(o[2 * jj + 1], a0, a1, a2, a3, b2, b3);
                }
            }
        }
    }

    // lsum[0] = full row sum for row wi+row; lsum[2] for row wi+row+8.
    float inv0 = 1.f / lsum[0];
    float inv1 = 1.f / lsum[2];

    __syncthreads();
#pragma unroll
    for (int df = 0; df < 8; df++) {
        int d = df * 8 + colk * 2;
        *(__half2*)&Os[(wi + row) * KSM + d]     = __floats2half2_rn(o[df][0] * inv0, o[df][1] * inv0);
        *(__half2*)&Os[(wi + row + 8) * KSM + d] = __floats2half2_rn(o[df][2] * inv1, o[df][3] * inv1);
    }
    __syncthreads();

    __half* ob = g_attn + ((size_t)b * NL + i0) * HD + h * 64;
#pragma unroll
    for (int t = 0; t < 4; t++) {
        int v  = tid + t * 256;
        int rw = v >> 3;
        int ch = (v & 7) * 8;
        *(uint4*)(ob + (size_t)rw * HD + ch) = *(const uint4*)(&Os[rw * KSM + ch]);
    }
}

// ---------------------------------------------------------------------------
// Launch
// ---------------------------------------------------------------------------
extern "C" void kernel_launch(void* const* d_in, const int* in_sizes, int n_in,
                              void* d_out, int out_size)
{
    const float* x     = (const float*)d_in[0];   // [4, 512, 2048]
    const float* w_qkv = (const float*)d_in[1];   // [512, 1536]
    const float* w_out = (const float*)d_in[2];   // [512, 512]
    const float* b_out = (const float*)d_in[3];   // [512]
    float* y = (float*)d_out;                     // [4, 512, 2048]

    __half *xt, *wqt, *wot, *attn;
    cudaGetSymbolAddress((void**)&xt,   g_xt);
    cudaGetSymbolAddress((void**)&wqt,  g_wqt);
    cudaGetSymbolAddress((void**)&wot,  g_wot);
    cudaGetSymbolAddress((void**)&attn, g_attn);

    // 0) fp16-rounding transposes to k-minor layouts (single launch)
    cvt_all<<<5120, dim3(32, 8)>>>(x, w_qkv, w_out, xt, wqt, wot);

    const int gsmem = 3 * 2 * 128 * GSH * (int)sizeof(__half);   // 110,592 B
    cudaFuncSetAttribute(gemm_f16, cudaFuncAttributeMaxDynamicSharedMemorySize, gsmem);

    // 1) QKV projection: M=1536, N=2048, K=512 -> g_q/g_k/g_v (fp16)
    {
        dim3 grid(NL / 128, F3 / 128, NB);
        gemm_f16<<<grid, 256, gsmem>>>(wqt, xt, nullptr, nullptr, F3, NL, NC, 1);
    }

    // 2) Flash attention -> g_attn[b][l][c] (fp16)
    {
        const int asmem = (128 * QSM + 2 * 128 * KSM + 2 * 64 * VSM) * (int)sizeof(__half); // 90,112 B
        cudaFuncSetAttribute(attn_f16, cudaFuncAttributeMaxDynamicSharedMemorySize, asmem);
        dim3 grid(NL / 128, NB * HEADS);
        attn_f16<<<grid, 256, asmem>>>();
    }

    // 3) Output projection + bias: M=512, N=2048, K=512 -> fp32 out
    {
        dim3 grid(NL / 128, HD / 128, NB);
        gemm_f16<<<grid, 256, gsmem>>>(wot, attn, y, b_out, NC, NL, HD, 0);
    }
}

// round 16
// speedup vs baseline: 1.0605x; 1.0007x over previous
#include <cuda_runtime.h>
#include <cuda_fp16.h>
#include <cstdint>

#define HEADS 8
#define DIM_HEAD 64
#define NB 4
#define NC 512
#define NL 2048
#define HD 512
#define F3 1536
#define QSCALE (0.125f * 1.4426950408889634f)

// Scratch (device globals; no allocations allowed) — all fp16
__device__ __half g_q[(size_t)NB * HEADS * NL * DIM_HEAD];   // [b,h][l][d]  pre-scaled
__device__ __half g_k[(size_t)NB * HEADS * NL * DIM_HEAD];   // [b,h][l][d]
__device__ __half g_v[(size_t)NB * HEADS * DIM_HEAD * NL];   // [b,h][d][l]
__device__ __half g_attn[(size_t)NB * NL * HD];              // [b][l][c]
__device__ __half g_xt[(size_t)NB * NL * NC];                // [b][l][c]
__device__ __half g_wqt[(size_t)F3 * NC];                    // [f][c]
__device__ __half g_wot[(size_t)NC * HD];                    // [c_out][hd]

__device__ __forceinline__ void mma_f16(float d[4],
                                        uint32_t a0, uint32_t a1, uint32_t a2, uint32_t a3,
                                        uint32_t b0, uint32_t b1) {
    asm volatile(
        "mma.sync.aligned.m16n8k16.row.col.f32.f16.f16.f32 "
        "{%0,%1,%2,%3}, {%4,%5,%6,%7}, {%8,%9}, {%0,%1,%2,%3};"
        : "+f"(d[0]), "+f"(d[1]), "+f"(d[2]), "+f"(d[3])
        : "r"(a0), "r"(a1), "r"(a2), "r"(a3), "r"(b0), "r"(b1));
}

__device__ __forceinline__ void cp16(void* smem, const void* g) {
    uint32_t s = (uint32_t)__cvta_generic_to_shared(smem);
    asm volatile("cp.async.cg.shared.global [%0], [%1], 16;" :: "r"(s), "l"(g));
}
// L1-cached variant for reused (weight) operands
__device__ __forceinline__ void cp16ca(void* smem, const void* g) {
    uint32_t s = (uint32_t)__cvta_generic_to_shared(smem);
    asm volatile("cp.async.ca.shared.global [%0], [%1], 16;" :: "r"(s), "l"(g));
}
#define CP_COMMIT() asm volatile("cp.async.commit_group;")
#define CP_WAIT(n)  asm volatile("cp.async.wait_group %0;" :: "n"(n))

__device__ __forceinline__ void ldsm4(uint32_t& r0, uint32_t& r1, uint32_t& r2, uint32_t& r3,
                                      const __half* p) {
    uint32_t a = (uint32_t)__cvta_generic_to_shared(p);
    asm volatile("ldmatrix.sync.aligned.m8n8.x4.shared.b16 {%0,%1,%2,%3}, [%4];"
                 : "=r"(r0), "=r"(r1), "=r"(r2), "=r"(r3) : "r"(a));
}

// two fp16 exp2's in one MUFU op
__device__ __forceinline__ uint32_t h2ex2(uint32_t x) {
    uint32_t r;
    asm("ex2.approx.f16x2 %0, %1;" : "=r"(r) : "r"(x));
    return r;
}

// ---------------------------------------------------------------------------
// Merged transpose + fp16 round for all three inputs (one launch).
// ---------------------------------------------------------------------------
__global__ void cvt_all(const float* __restrict__ x,
                        const float* __restrict__ wq,
                        const float* __restrict__ wo,
                        __half* __restrict__ xt,
                        __half* __restrict__ wqt,
                        __half* __restrict__ wot)
{
    __shared__ float t[32][33];
    int bid = blockIdx.x;
    const float* in;
    __half* out;
    int C;
    if (bid < 768)        { in = wq; out = wqt; C = F3; }
    else if (bid < 1024)  { bid -= 768;  in = wo; out = wot; C = HD; }
    else {
        bid -= 1024;
        int bz = bid >> 10;
        bid &= 1023;
        in  = x  + (size_t)bz * NC * NL;
        out = xt + (size_t)bz * NL * NC;
        C = NL;
    }
    const int tpr = C / 32;
    const int c0 = (bid % tpr) * 32, r0 = (bid / tpr) * 32;
    const int tx = threadIdx.x, ty = threadIdx.y;
#pragma unroll
    for (int rr = ty; rr < 32; rr += 8)
        t[rr][tx] = in[(size_t)(r0 + rr) * C + c0 + tx];
    __syncthreads();
#pragma unroll
    for (int rr = ty; rr < 32; rr += 8)
        out[(size_t)(c0 + rr) * NC + r0 + tx] = __float2half_rn(t[tx][rr]);
}

// ---------------------------------------------------------------------------
// GEMM (unified): Y[b][m][n] = sum_k W'[m][k] * X'[b][n][k].
// CTA 128x128, BK=64, 3-stage cp.async, one barrier per k-iter, 8 warps 32x64.
// A (weights) staged via cp.async.ca (L1-cached, reused across CTAs);
// B streams via .cg.
// mode 1: route to g_q (scaled)/g_k/g_v fp16.   mode 0: Y fp32 + bias (B .ca).
// ---------------------------------------------------------------------------
#define GSH 72
__global__ __launch_bounds__(256) void gemm_f16(
    const __half* __restrict__ W, const __half* __restrict__ X,
    float* __restrict__ Y, const float* __restrict__ bias,
    int M, int N, int K, int mode)
{
    extern __shared__ __half gsm[];
    const int STAGE = 2 * 128 * GSH;

    const int b = blockIdx.z;
    const __half* Xb = X + (size_t)b * N * K;

    const int m0 = blockIdx.y * 128;
    const int n0 = blockIdx.x * 128;
    const int tid  = threadIdx.x;
    const int warp = tid >> 5, lane = tid & 31;
    const int row  = lane >> 2, colk = lane & 3;
    const int wm = (warp >> 1) * 32, wn = (warp & 1) * 64;
    const int aRow = (lane & 7) + ((lane >> 3) & 1) * 8, aCol = (lane >> 4) * 8;
    const int bRow = (lane & 7) + (lane >> 4) * 8,       bCol = ((lane >> 3) & 1) * 8;

    float acc[2][8][4];
#pragma unroll
    for (int i = 0; i < 2; i++)
#pragma unroll
        for (int j = 0; j < 8; j++)
#pragma unroll
            for (int c = 0; c < 4; c++) acc[i][j][c] = 0.f;

    auto load_stage = [&](int st, int k0) {
        __half* A = gsm + st * STAGE;
        __half* B = A + 128 * GSH;
#pragma unroll
        for (int t = 0; t < 4; t++) {
            int v  = tid + t * 256;
            int rw = v >> 3;
            int ch = (v & 7) * 8;
            cp16ca(&A[rw * GSH + ch], W  + (size_t)(m0 + rw) * K + k0 + ch);
            if (mode == 0)
                cp16ca(&B[rw * GSH + ch], Xb + (size_t)(n0 + rw) * K + k0 + ch);
            else
                cp16(&B[rw * GSH + ch], Xb + (size_t)(n0 + rw) * K + k0 + ch);
        }
    };

    const int KT = K / 64;
    load_stage(0, 0);  CP_COMMIT();
    load_stage(1, 64); CP_COMMIT();

    int st = 0;
    for (int kt = 0; kt < KT; kt++) {
        CP_WAIT(1);
        __syncthreads();
        if (kt + 2 < KT) {
            load_stage((kt + 2) % 3, (kt + 2) * 64);
            CP_COMMIT();
        }
        const __half* A = gsm + st * STAGE;
        const __half* B = A + 128 * GSH;
        st = (st + 1 == 3) ? 0 : st + 1;

#pragma unroll
        for (int ks = 0; ks < 4; ks++) {
            const int kb = ks * 16;
            uint32_t a[2][4];
            ldsm4(a[0][0], a[0][1], a[0][2], a[0][3], &A[(wm + aRow) * GSH + kb + aCol]);
            ldsm4(a[1][0], a[1][1], a[1][2], a[1][3], &A[(wm + 16 + aRow) * GSH + kb + aCol]);
#pragma unroll
            for (int jj = 0; jj < 4; jj++) {
                uint32_t b0, b1, b2, b3;
                ldsm4(b0, b1, b2, b3, &B[(wn + jj * 16 + bRow) * GSH + kb + bCol]);
#pragma unroll
                for (int i = 0; i < 2; i++) {
                    mma_f16(acc[i][2 * jj],     a[i][0], a[i][1], a[i][2], a[i][3], b0, b1);
                    mma_f16(acc[i][2 * jj + 1], a[i][0], a[i][1], a[i][2], a[i][3], b2, b3);
                }
            }
        }
    }

    if (mode == 1) {
        const int sec = m0 >> 9;              // 0=q, 1=k, 2=v (CTA-uniform)
#pragma unroll
        for (int i = 0; i < 2; i++) {
            int mloc = (m0 & 511) + wm + 16 * i + row;
            int hh = mloc >> 6, dd = mloc & 63;
            size_t bh = (size_t)b * HEADS + hh;
#pragma unroll
            for (int j = 0; j < 8; j++) {
                int n = n0 + wn + j * 8 + colk * 2;
                float v0 = acc[i][j][0], v1 = acc[i][j][1];
                float v2 = acc[i][j][2], v3 = acc[i][j][3];
                if (sec == 0) {
                    __half* p = g_q + (bh * NL + n) * 64 + dd;
                    p[0]  = __float2half_rn(v0 * QSCALE);
                    p[64] = __float2half_rn(v1 * QSCALE);
                    p[8]  = __float2half_rn(v2 * QSCALE);
                    p[72] = __float2half_rn(v3 * QSCALE);
                } else if (sec == 1) {
                    __half* p = g_k + (bh * NL + n) * 64 + dd;
                    p[0]  = __float2half_rn(v0);
                    p[64] = __float2half_rn(v1);
                    p[8]  = __float2half_rn(v2);
                    p[72] = __float2half_rn(v3);
                } else {
                    __half* p = g_v + (bh * 64 + dd) * NL + n;
                    *(__half2*)p            = __floats2half2_rn(v0, v1);
                    *(__half2*)(p + 8 * NL) = __floats2half2_rn(v2, v3);
                }
            }
        }
    } else {
        float* Yb = Y + (size_t)b * M * N;
#pragma unroll
        for (int i = 0; i < 2; i++) {
            int m = m0 + wm + 16 * i + row;
            float bv0 = bias[m], bv1 = bias[m + 8];
#pragma unroll
            for (int j = 0; j < 8; j++) {
                int n = n0 + wn + j * 8 + colk * 2;
                Yb[(size_t)m * N + n]           = acc[i][j][0] + bv0;
                Yb[(size_t)m * N + n + 1]       = acc[i][j][1] + bv0;
                Yb[(size_t)(m + 8) * N + n]     = acc[i][j][2] + bv1;
                Yb[(size_t)(m + 8) * N + n + 1] = acc[i][j][3] + bv1;
            }
        }
    }
}

// ---------------------------------------------------------------------------
// Flash attention (unchanged R15): fp16 mma + LDSM, 128-query CTA, 256 thr,
// double-buffered 128-key stages, hoisted Q fragments, register-resident P,
// no max-subtraction, tensor-core row sums. Smem 90,112 B -> 2 CTAs/SM.
// ---------------------------------------------------------------------------
#define QSM 72
#define KSM 72
#define VSM 136
__global__ __launch_bounds__(256, 2) void attn_f16(void)
{
    extern __shared__ __half sm[];
    __half* Qs = sm;                     // [128][72]     (i, d)
    __half* Ks = Qs + 128 * QSM;         // [2][128][72]  (j, d)
    __half* Vs = Ks + 2 * 128 * KSM;     // [2][64][136]  (d, j)
    __half* Os = Ks;                     // epilogue reuse

    const int bh = blockIdx.y;
    const int b  = bh >> 3;
    const int h  = bh & 7;
    const int i0 = blockIdx.x * 128;

    const __half* qb = g_q + (size_t)bh * NL * 64;
    const __half* kb = g_k + (size_t)bh * NL * 64;
    const __half* vb = g_v + (size_t)bh * 64 * NL;

    const int tid  = threadIdx.x;
    const int warp = tid >> 5, lane = tid & 31;
    const int row  = lane >> 2, colk = lane & 3;
    const int wi   = warp * 16;
    const int aRow = (lane & 7) + ((lane >> 3) & 1) * 8, aCol = (lane >> 4) * 8;
    const int bRow = (lane & 7) + (lane >> 4) * 8,       bCol = ((lane >> 3) & 1) * 8;
    const uint32_t ONES = 0x3C003C00u;   // half2(1.0, 1.0)

    auto load_k = [&](int stg, int j0) {
        __half* K = Ks + stg * 128 * KSM;
#pragma unroll
        for (int t = 0; t < 4; t++) {
            int v  = tid + t * 256;
            int rw = v >> 3;
            int ch = (v & 7) * 8;
            cp16(&K[rw * KSM + ch], kb + (size_t)(j0 + rw) * 64 + ch);
        }
    };
    auto load_v = [&](int stg, int j0) {
        __half* V = Vs + stg * 64 * VSM;
#pragma unroll
        for (int t = 0; t < 4; t++) {
            int v  = tid + t * 256;
            int rw = v >> 4;
            int ch = (v & 15) * 8;
            cp16(&V[rw * VSM + ch], vb + (size_t)rw * NL + j0 + ch);
        }
    };

#pragma unroll
    for (int t = 0; t < 4; t++) {
        int v  = tid + t * 256;
        int rw = v >> 3;
        int ch = (v & 7) * 8;
        cp16(&Qs[rw * QSM + ch], qb + (size_t)(i0 + rw) * 64 + ch);
    }
    load_k(0, 0);
    load_v(0, 0);
    CP_COMMIT();

    CP_WAIT(0);
    __syncthreads();
    uint32_t qf[4][4];
#pragma unroll
    for (int kc = 0; kc < 4; kc++)
        ldsm4(qf[kc][0], qf[kc][1], qf[kc][2], qf[kc][3],
              &Qs[(wi + aRow) * QSM + kc * 16 + aCol]);

    float lsum[4];
#pragma unroll
    for (int c = 0; c < 4; c++) lsum[c] = 0.f;
    float o[8][4];
#pragma unroll
    for (int df = 0; df < 8; df++)
#pragma unroll
        for (int c = 0; c < 4; c++) o[df][c] = 0.f;

    const int NT = NL / 128;
    for (int jt = 0; jt < NT; jt++) {
        if (jt > 0) {
            CP_WAIT(0);
            __syncthreads();
        }
        if (jt + 1 < NT) {
            load_k((jt + 1) & 1, (jt + 1) * 128);
            load_v((jt + 1) & 1, (jt + 1) * 128);
            CP_COMMIT();
        }
        const __half* K = Ks + (jt & 1) * 128 * KSM;
        const __half* V = Vs + (jt & 1) * 64 * VSM;

#pragma unroll
        for (int sub = 0; sub < 2; sub++) {
            const int jb = sub * 64;

            // S = Q K^T
            float s[8][4];
#pragma unroll
            for (int jf = 0; jf < 8; jf++)
#pragma unroll
                for (int c = 0; c < 4; c++) s[jf][c] = 0.f;

#pragma unroll
            for (int kc = 0; kc < 4; kc++) {
                const int kb16 = kc * 16;
#pragma unroll
                for (int jj = 0; jj < 4; jj++) {
                    uint32_t b0, b1, b2, b3;
                    ldsm4(b0, b1, b2, b3, &K[(jb + jj * 16 + bRow) * KSM + kb16 + bCol]);
                    mma_f16(s[2 * jj],     qf[kc][0], qf[kc][1], qf[kc][2], qf[kc][3], b0, b1);
                    mma_f16(s[2 * jj + 1], qf[kc][0], qf[kc][1], qf[kc][2], qf[kc][3], b2, b3);
                }
            }

            // P = exp2(S); fp16 pairs are the PV A-fragments directly.
            uint32_t pl[8], ph[8];
#pragma unroll
            for (int jf = 0; jf < 8; jf++) {
                __half2 d0 = __floats2half2_rn(s[jf][0], s[jf][1]);
                __half2 d1 = __floats2half2_rn(s[jf][2], s[jf][3]);
                pl[jf] = h2ex2(*(uint32_t*)&d0);
                ph[jf] = h2ex2(*(uint32_t*)&d1);
            }

            // O += P V^T ; l += P * ones (on the tensor pipe)
#pragma unroll
            for (int kc = 0; kc < 4; kc++) {
                const int kb16 = jb + kc * 16;
                uint32_t a0 = pl[2 * kc],     a1 = ph[2 * kc];
                uint32_t a2 = pl[2 * kc + 1], a3 = ph[2 * kc + 1];
                mma_f16(lsum, a0, a1, a2, a3, ONES, ONES);
#pragma unroll
                for (int jj = 0; jj < 4; jj++) {
                    uint32_t b0, b1, b2, b3;
                    ldsm4(b0, b1, b2, b3, &V[(jj * 16 + bRow) * VSM + kb16 + bCol]);
                    mma_f16(o[2 * jj],     a0, a1, a2, a3, b0, b1);
                    mma_f16(o[2 * jj + 1], a0, a1, a2, a3, b2, b3);
                }
            }
        }
    }

    float inv0 = 1.f / lsum[0];
    float inv1 = 1.f / lsum[2];

    __syncthreads();
#pragma unroll
    for (int df = 0; df < 8; df++) {
        int d = df * 8 + colk * 2;
        *(__half2*)&Os[(wi + row) * KSM + d]     = __floats2half2_rn(o[df][0] * inv0, o[df][1] * inv0);
        *(__half2*)&Os[(wi + row + 8) * KSM + d] = __floats2half2_rn(o[df][2] * inv1, o[df][3] * inv1);
    }
    __syncthreads();

    __half* ob = g_attn + ((size_t)b * NL + i0) * HD + h * 64;
#pragma unroll
    for (int t = 0; t < 4; t++) {
        int v  = tid + t * 256;
        int rw = v >> 3;
        int ch = (v & 7) * 8;
        *(uint4*)(ob + (size_t)rw * HD + ch) = *(const uint4*)(&Os[rw * KSM + ch]);
    }
}

// ---------------------------------------------------------------------------
// Launch
// ---------------------------------------------------------------------------
extern "C" void kernel_launch(void* const* d_in, const int* in_sizes, int n_in,
                              void* d_out, int out_size)
{
    const float* x     = (const float*)d_in[0];   // [4, 512, 2048]
    const float* w_qkv = (const float*)d_in[1];   // [512, 1536]
    const float* w_out = (const float*)d_in[2];   // [512, 512]
    const float* b_out = (const float*)d_in[3];   // [512]
    float* y = (float*)d_out;                     // [4, 512, 2048]

    __half *xt, *wqt, *wot, *attn;
    cudaGetSymbolAddress((void**)&xt,   g_xt);
    cudaGetSymbolAddress((void**)&wqt,  g_wqt);
    cudaGetSymbolAddress((void**)&wot,  g_wot);
    cudaGetSymbolAddress((void**)&attn, g_attn);

    // 0) fp16-rounding transposes to k-minor layouts (single launch)
    cvt_all<<<5120, dim3(32, 8)>>>(x, w_qkv, w_out, xt, wqt, wot);

    const int gsmem = 3 * 2 * 128 * GSH * (int)sizeof(__half);   // 110,592 B
    cudaFuncSetAttribute(gemm_f16, cudaFuncAttributeMaxDynamicSharedMemorySize, gsmem);

    // 1) QKV projection: M=1536, N=2048, K=512 -> g_q/g_k/g_v (fp16)
    {
        dim3 grid(NL / 128, F3 / 128, NB);
        gemm_f16<<<grid, 256, gsmem>>>(wqt, xt, nullptr, nullptr, F3, NL, NC, 1);
    }

    // 2) Flash attention -> g_attn[b][l][c] (fp16)
    {
        const int asmem = (128 * QSM + 2 * 128 * KSM + 2 * 64 * VSM) * (int)sizeof(__half); // 90,112 B
        cudaFuncSetAttribute(attn_f16, cudaFuncAttributeMaxDynamicSharedMemorySize, asmem);
        dim3 grid(NL / 128, NB * HEADS);
        attn_f16<<<grid, 256, asmem>>>();
    }

    // 3) Output projection + bias: M=512, N=2048, K=512 -> fp32 out
    {
        dim3 grid(NL / 128, HD / 128, NB);
        gemm_f16<<<grid, 256, gsmem>>>(wot, attn, y, b_out, NC, NL, HD, 0);
    }
}